// round 12
// baseline (speedup 1.0000x reference)
#include <cuda_runtime.h>
#include <cuda_fp16.h>
#include <stdint.h>

#define BATCH 16384
#define DIM   64
#define HID   64
#define TROWS 256     // batch rows per CTA (64 per warp)
#define THREADS 128

// ---- scratch: pre-converted fp16, pre-swizzled ----
__device__ __align__(16) half g_xh[BATCH * 64];        // 2 MB
__device__ __align__(16) half g_w1h[63 * 64 * 64];     // 516 KB (masked)
__device__ __align__(16) half g_w2h[63 * 64 * 64];     // 516 KB

// ---------------- PTX helpers ----------------
__device__ __forceinline__ uint32_t smem_u32(const void* p) {
    return (uint32_t)__cvta_generic_to_shared(p);
}
__device__ __forceinline__ void cp16(uint32_t dst, const void* src) {
    asm volatile("cp.async.cg.shared.global [%0], [%1], 16;" :: "r"(dst), "l"(src));
}
__device__ __forceinline__ void cp_commit() {
    asm volatile("cp.async.commit_group;" ::: "memory");
}
__device__ __forceinline__ void cp_wait_all() {
    asm volatile("cp.async.wait_group 0;" ::: "memory");
}
__device__ __forceinline__ void ldmx4(uint32_t& r0, uint32_t& r1, uint32_t& r2, uint32_t& r3, uint32_t addr) {
    asm volatile("ldmatrix.sync.aligned.m8n8.x4.shared.b16 {%0,%1,%2,%3}, [%4];"
                 : "=r"(r0), "=r"(r1), "=r"(r2), "=r"(r3) : "r"(addr));
}
__device__ __forceinline__ void ldmx4t(uint32_t& r0, uint32_t& r1, uint32_t& r2, uint32_t& r3, uint32_t addr) {
    asm volatile("ldmatrix.sync.aligned.m8n8.x4.trans.shared.b16 {%0,%1,%2,%3}, [%4];"
                 : "=r"(r0), "=r"(r1), "=r"(r2), "=r"(r3) : "r"(addr));
}
__device__ __forceinline__ void ldmx2t(uint32_t& r0, uint32_t& r1, uint32_t addr) {
    asm volatile("ldmatrix.sync.aligned.m8n8.x2.trans.shared.b16 {%0,%1}, [%2];"
                 : "=r"(r0), "=r"(r1) : "r"(addr));
}
// D = A*B + C (always accumulates into c)
__device__ __forceinline__ void mma16816(float* c,
    uint32_t a0, uint32_t a1, uint32_t a2, uint32_t a3, uint32_t b0, uint32_t b1) {
    asm volatile("mma.sync.aligned.m16n8k16.row.col.f32.f16.f16.f32 "
                 "{%0,%1,%2,%3}, {%4,%5,%6,%7}, {%8,%9}, {%0,%1,%2,%3};"
                 : "+f"(c[0]), "+f"(c[1]), "+f"(c[2]), "+f"(c[3])
                 : "r"(a0), "r"(a1), "r"(a2), "r"(a3), "r"(b0), "r"(b1));
}
__device__ __forceinline__ uint32_t packh2(float lo, float hi) {
    __half2 h = __floats2half2_rn(lo, hi);
    return *reinterpret_cast<uint32_t*>(&h);
}
// swizzled halfword offset: 64 halves/row, 8 chunks of 8 halves (16B),
// chunk XOR (row&7) -> conflict-free ldmatrix
__device__ __forceinline__ int swz(int row, int chunk) {
    return row * 64 + ((chunk ^ (row & 7)) << 3);
}

// ============ merged pre-kernel: x + W1(masked) + W2 fp32 -> fp16, swizzled ============
__global__ void __launch_bounds__(256) convert_all_kernel(const float* __restrict__ x,
                                                          const float* __restrict__ W1,
                                                          const float* __restrict__ W2) {
    const int b = blockIdx.x;
    const int tid = threadIdx.x;
    if (b < 256) {
        const int g0 = b * 256 + tid;
        #pragma unroll
        for (int k = 0; k < 4; k++) {
            int g = g0 + k * 65536;
            float4 v = reinterpret_cast<const float4*>(x)[g];
            int row = g >> 4, c16 = g & 15;
            int chunk = c16 >> 1;
            half2* d = reinterpret_cast<half2*>(g_xh + row * 64 + ((chunk ^ (row & 7)) << 3) + (c16 & 1) * 4);
            d[0] = __floats2half2_rn(v.x, v.y);
            d[1] = __floats2half2_rn(v.z, v.w);
        }
    } else {
        const int g0 = (b - 256) * 256 + tid;
        #pragma unroll
        for (int k = 0; k < 2; k++) {
            int g = g0 + k * 32256;
            float4 v1 = reinterpret_cast<const float4*>(W1)[g];
            float4 v2 = reinterpret_cast<const float4*>(W2)[g];
            int net = g >> 10;
            int rem = g & 1023;
            int kk  = rem >> 4;
            int c16 = rem & 15;
            if (kk > net) v1 = make_float4(0.f, 0.f, 0.f, 0.f);   // autoregressive mask
            int chunk = c16 >> 1;
            int base = net * 4096 + kk * 64 + ((chunk ^ (kk & 7)) << 3) + (c16 & 1) * 4;
            half2* d1 = reinterpret_cast<half2*>(g_w1h + base);
            d1[0] = __floats2half2_rn(v1.x, v1.y);
            d1[1] = __floats2half2_rn(v1.z, v1.w);
            half2* d2 = reinterpret_cast<half2*>(g_w2h + base);
            d2[0] = __floats2half2_rn(v2.x, v2.y);
            d2[1] = __floats2half2_rn(v2.z, v2.w);
        }
    }
}

// ============ main kernel ============
// grid (32, 64): blockIdx.x = network-pair {p, 64-p} (uniform kcN work), y = batch tile.
// One x tile serves both networks; no mid-kernel barriers.
__global__ void __launch_bounds__(THREADS, 3)
ar_kernel(const float* __restrict__ w0, const float* __restrict__ b0,
          const float* __restrict__ v0, const float* __restrict__ c0,
          const float* __restrict__ B1, const float* __restrict__ B2,
          const float* __restrict__ W3, const float* __restrict__ B3,
          float* __restrict__ out)
{
    extern __shared__ char dsm[];
    half* sX   = (half*)dsm;               // 32 KB
    half* sW1  = (half*)(dsm + 32768);     // 2 x 8 KB
    half* sW2  = (half*)(dsm + 49152);     // 2 x 8 KB
    half* sW3t = (half*)(dsm + 65536);     // 2 x 1 KB  [k][n<=8] layer-3 B tiles
    __shared__ float sB1[2][64], sB2[2][64];
    __shared__ float sb3[2][2];

    const int tid  = threadIdx.x;
    const int pair = blockIdx.x;           // 0..31
    const int bty  = blockIdx.y;           // 0..63
    const int netA = (pair == 0) ? 32 : pair;
    const int netB = (pair == 0) ? 0  : 64 - pair;
    const int m0   = bty * TROWS;

    // ---- async fetch: x tile (32KB) + weights for both nets (32KB) ----
    {
        const uint32_t ax = smem_u32(sX);
        const half* gx = g_xh + (size_t)m0 * 64;
        #pragma unroll
        for (int r = 0; r < 16; r++) {
            int c = r * THREADS + tid;
            cp16(ax + c * 16, gx + c * 8);
        }
    }
    #pragma unroll
    for (int nn = 0; nn < 2; nn++) {
        const int net = nn ? netB : netA;
        if (net > 0) {
            const int i = net - 1;
            const uint32_t a1 = smem_u32(sW1 + nn * 4096);
            const uint32_t a2 = smem_u32(sW2 + nn * 4096);
            const half* gw1 = g_w1h + i * 4096;
            const half* gw2 = g_w2h + i * 4096;
            #pragma unroll
            for (int r = 0; r < 4; r++) {
                int c = r * THREADS + tid;
                cp16(a1 + c * 16, gw1 + c * 8);
                cp16(a2 + c * 16, gw2 + c * 8);
            }
            if (tid < 64) {
                sB1[nn][tid] = B1[i * 64 + tid];
                sB2[nn][tid] = B2[i * 64 + tid];
                half2* d = reinterpret_cast<half2*>(sW3t + nn * 512 + tid * 8);
                d[0] = __floats2half2_rn(W3[i * 128 + tid * 2 + 0], W3[i * 128 + tid * 2 + 1]);
                d[1] = __floats2half2_rn(0.f, 0.f);
                d[2] = __floats2half2_rn(0.f, 0.f);
                d[3] = __floats2half2_rn(0.f, 0.f);
            }
            if (tid == 0) { sb3[nn][0] = B3[i * 2 + 0]; sb3[nn][1] = B3[i * 2 + 1]; }
        }
    }
    cp_commit();
    cp_wait_all();
    __syncthreads();

    const int lane = tid & 31;
    const int warp = tid >> 5;

    #pragma unroll
    for (int nn = 0; nn < 2; nn++) {
        const int net = nn ? netB : netA;

        if (net == 0) {
            // constant network 0: output identical across batch
            float s = c0[0], t = c0[1];
            #pragma unroll
            for (int j = 0; j < HID; j++) {
                float h = fmaxf(w0[j] + b0[j], 0.f);
                s += h * v0[j * 2 + 0];
                t += h * v0[j * 2 + 1];
            }
            s = fminf(fmaxf(s, -5.f), 5.f);
            #pragma unroll
            for (int k = 0; k < TROWS; k += THREADS) {
                int r = m0 + k + tid;
                out[r * DIM + 0] = s;
                out[BATCH * DIM + r * DIM + 0] = t;
            }
            continue;
        }

        const int kcN = (net + 15) >> 4;   // masked K chunks for layer 1 (1..4)
        const float b3s = sb3[nn][0];
        const float b3t = sb3[nn][1];
        const half* W1n = sW1 + nn * 4096;
        const half* W2n = sW2 + nn * 4096;

        // layer-3 B fragments: 4 kc x {b0,b1}
        uint32_t b3f[4][2];
        {
            int krl = (lane & 7) + 8 * ((lane >> 3) & 1);
            #pragma unroll
            for (int kc = 0; kc < 4; kc++) {
                ldmx2t(b3f[kc][0], b3f[kc][1], smem_u32(sW3t + nn * 512 + (kc * 16 + krl) * 8));
            }
        }

        // packed h1 (fp16x2) A-fragments for layer 2: [mt][16]
        uint32_t packed[4][16];

        // ================= PHASE 1: h1 = relu(X @ W1m + B1) =================
        #pragma unroll
        for (int j2h = 0; j2h < 2; j2h++) {
            uint32_t b1[4][2][4];
            #pragma unroll
            for (int kc = 0; kc < 4; kc++) if (kc < kcN) {
                #pragma unroll
                for (int j2l = 0; j2l < 2; j2l++) {
                    int j2 = j2h * 2 + j2l;
                    int kr = kc * 16 + (lane & 7) + 8 * ((lane >> 3) & 1);
                    int chunk = j2 * 2 + (lane >> 4);
                    ldmx4t(b1[kc][j2l][0], b1[kc][j2l][1], b1[kc][j2l][2], b1[kc][j2l][3],
                           smem_u32(W1n + swz(kr, chunk)));
                }
            }
            #pragma unroll
            for (int mt = 0; mt < 4; mt++) {
                float acc[4][4];
                #pragma unroll
                for (int jj = 0; jj < 4; jj++) {   // bias-init accumulators
                    int n0 = (j2h * 4 + jj) * 8 + 2 * (lane & 3);
                    acc[jj][0] = sB1[nn][n0];
                    acc[jj][1] = sB1[nn][n0 + 1];
                    acc[jj][2] = acc[jj][0];
                    acc[jj][3] = acc[jj][1];
                }
                #pragma unroll
                for (int kc = 0; kc < 4; kc++) if (kc < kcN) {
                    uint32_t a0, a1, a2, a3;
                    int r = warp * 64 + mt * 16 + (lane & 15);
                    int chunk = kc * 2 + (lane >> 4);
                    ldmx4(a0, a1, a2, a3, smem_u32(sX + swz(r, chunk)));
                    #pragma unroll
                    for (int j2l = 0; j2l < 2; j2l++) {
                        mma16816(acc[2 * j2l + 0], a0, a1, a2, a3, b1[kc][j2l][0], b1[kc][j2l][1]);
                        mma16816(acc[2 * j2l + 1], a0, a1, a2, a3, b1[kc][j2l][2], b1[kc][j2l][3]);
                    }
                }
                #pragma unroll
                for (int jj = 0; jj < 4; jj++) {
                    packed[mt][j2h * 8 + jj * 2 + 0] = packh2(fmaxf(acc[jj][0], 0.f), fmaxf(acc[jj][1], 0.f));
                    packed[mt][j2h * 8 + jj * 2 + 1] = packh2(fmaxf(acc[jj][2], 0.f), fmaxf(acc[jj][3], 0.f));
                }
            }
        }

        // ====== PHASE 2+3: h2 = relu(h1 @ W2 + B2); [s,t] = h2 @ W3 + B3 (mma) ======
        float acc3[4][4];
        #pragma unroll
        for (int mt = 0; mt < 4; mt++) {
            acc3[mt][0] = b3s; acc3[mt][1] = b3t;
            acc3[mt][2] = b3s; acc3[mt][3] = b3t;
        }

        #pragma unroll
        for (int j2h = 0; j2h < 2; j2h++) {
            uint32_t b2[4][2][4];
            #pragma unroll
            for (int kc = 0; kc < 4; kc++) {
                #pragma unroll
                for (int j2l = 0; j2l < 2; j2l++) {
                    int j2 = j2h * 2 + j2l;
                    int kr = kc * 16 + (lane & 7) + 8 * ((lane >> 3) & 1);
                    int chunk = j2 * 2 + (lane >> 4);
                    ldmx4t(b2[kc][j2l][0], b2[kc][j2l][1], b2[kc][j2l][2], b2[kc][j2l][3],
                           smem_u32(W2n + swz(kr, chunk)));
                }
            }
            #pragma unroll
            for (int mt = 0; mt < 4; mt++) {
                float acc[4][4];
                #pragma unroll
                for (int jj = 0; jj < 4; jj++) {   // bias-init accumulators
                    int n0 = (j2h * 4 + jj) * 8 + 2 * (lane & 3);
                    acc[jj][0] = sB2[nn][n0];
                    acc[jj][1] = sB2[nn][n0 + 1];
                    acc[jj][2] = acc[jj][0];
                    acc[jj][3] = acc[jj][1];
                }
                #pragma unroll
                for (int kc = 0; kc < 4; kc++) {
                    const uint32_t* a = &packed[mt][4 * kc];
                    #pragma unroll
                    for (int j2l = 0; j2l < 2; j2l++) {
                        mma16816(acc[2 * j2l + 0], a[0], a[1], a[2], a[3], b2[kc][j2l][0], b2[kc][j2l][1]);
                        mma16816(acc[2 * j2l + 1], a[0], a[1], a[2], a[3], b2[kc][j2l][2], b2[kc][j2l][3]);
                    }
                }
                // relu + pack h2 -> layer-3 A fragments (this j2h covers k = j2h*32..+31)
                uint32_t p2[8];
                #pragma unroll
                for (int jj = 0; jj < 4; jj++) {
                    p2[jj * 2 + 0] = packh2(fmaxf(acc[jj][0], 0.f), fmaxf(acc[jj][1], 0.f));
                    p2[jj * 2 + 1] = packh2(fmaxf(acc[jj][2], 0.f), fmaxf(acc[jj][3], 0.f));
                }
                mma16816(acc3[mt], p2[0], p2[1], p2[2], p2[3], b3f[j2h * 2 + 0][0], b3f[j2h * 2 + 0][1]);
                mma16816(acc3[mt], p2[4], p2[5], p2[6], p2[7], b3f[j2h * 2 + 1][0], b3f[j2h * 2 + 1][1]);
            }
        }

        // ---- store: lanes (lane&3)==0 hold cols 0 (scale) and 1 (translation) ----
        #pragma unroll
        for (int mt = 0; mt < 4; mt++) {
            if ((lane & 3) == 0) {
                int row = m0 + warp * 64 + mt * 16 + (lane >> 2);
                out[row * DIM + net] = fminf(fmaxf(acc3[mt][0], -5.f), 5.f);
                out[BATCH * DIM + row * DIM + net] = acc3[mt][1];
                int row8 = row + 8;
                out[row8 * DIM + net] = fminf(fmaxf(acc3[mt][2], -5.f), 5.f);
                out[BATCH * DIM + row8 * DIM + net] = acc3[mt][3];
            }
        }
    }
}

extern "C" void kernel_launch(void* const* d_in, const int* in_sizes, int n_in,
                              void* d_out, int out_size) {
    const float* x  = (const float*)d_in[0];
    const float* w0 = (const float*)d_in[1];
    const float* b0 = (const float*)d_in[2];
    const float* v0 = (const float*)d_in[3];
    const float* c0 = (const float*)d_in[4];
    const float* W1 = (const float*)d_in[5];
    const float* B1 = (const float*)d_in[6];
    const float* W2 = (const float*)d_in[7];
    const float* B2 = (const float*)d_in[8];
    const float* W3 = (const float*)d_in[9];
    const float* B3 = (const float*)d_in[10];

    convert_all_kernel<<<382, 256>>>(x, W1, W2);

    const int dyn_smem = 67584;   // 32K x + 16K W1 + 16K W2 + 2K W3t
    cudaFuncSetAttribute(ar_kernel, cudaFuncAttributeMaxDynamicSharedMemorySize, dyn_smem);

    dim3 grid(32, BATCH / TROWS);   // x = net pair (uniform work), y = batch tile
    ar_kernel<<<grid, THREADS, dyn_smem>>>(w0, b0, v0, c0, B1, B2, W3, B3, (float*)d_out);
}

// round 15
// speedup vs baseline: 1.2975x; 1.2975x over previous
#include <cuda_runtime.h>
#include <cuda_fp16.h>
#include <stdint.h>

#define BATCH 16384
#define DIM   64
#define HID   64
#define TROWS 256     // batch rows per CTA (64 per warp)
#define THREADS 128

// ---- scratch: pre-converted fp16, pre-swizzled ----
__device__ __align__(16) half g_xh[BATCH * 64];        // 2 MB
__device__ __align__(16) half g_w1h[63 * 64 * 64];     // 516 KB (masked)
__device__ __align__(16) half g_w2h[63 * 64 * 64];     // 516 KB

// ---------------- PTX helpers ----------------
__device__ __forceinline__ uint32_t smem_u32(const void* p) {
    return (uint32_t)__cvta_generic_to_shared(p);
}
__device__ __forceinline__ void cp16(uint32_t dst, const void* src) {
    asm volatile("cp.async.cg.shared.global [%0], [%1], 16;" :: "r"(dst), "l"(src));
}
__device__ __forceinline__ void cp_commit() {
    asm volatile("cp.async.commit_group;" ::: "memory");
}
__device__ __forceinline__ void cp_wait_all() {
    asm volatile("cp.async.wait_group 0;" ::: "memory");
}
__device__ __forceinline__ void ldmx4(uint32_t& r0, uint32_t& r1, uint32_t& r2, uint32_t& r3, uint32_t addr) {
    asm volatile("ldmatrix.sync.aligned.m8n8.x4.shared.b16 {%0,%1,%2,%3}, [%4];"
                 : "=r"(r0), "=r"(r1), "=r"(r2), "=r"(r3) : "r"(addr));
}
__device__ __forceinline__ void ldmx4t(uint32_t& r0, uint32_t& r1, uint32_t& r2, uint32_t& r3, uint32_t addr) {
    asm volatile("ldmatrix.sync.aligned.m8n8.x4.trans.shared.b16 {%0,%1,%2,%3}, [%4];"
                 : "=r"(r0), "=r"(r1), "=r"(r2), "=r"(r3) : "r"(addr));
}
__device__ __forceinline__ void ldmx2t(uint32_t& r0, uint32_t& r1, uint32_t addr) {
    asm volatile("ldmatrix.sync.aligned.m8n8.x2.trans.shared.b16 {%0,%1}, [%2];"
                 : "=r"(r0), "=r"(r1) : "r"(addr));
}
// D = A*B + C (always accumulates into c)
__device__ __forceinline__ void mma16816(float* c,
    uint32_t a0, uint32_t a1, uint32_t a2, uint32_t a3, uint32_t b0, uint32_t b1) {
    asm volatile("mma.sync.aligned.m16n8k16.row.col.f32.f16.f16.f32 "
                 "{%0,%1,%2,%3}, {%4,%5,%6,%7}, {%8,%9}, {%0,%1,%2,%3};"
                 : "+f"(c[0]), "+f"(c[1]), "+f"(c[2]), "+f"(c[3])
                 : "r"(a0), "r"(a1), "r"(a2), "r"(a3), "r"(b0), "r"(b1));
}
__device__ __forceinline__ uint32_t packh2(float lo, float hi) {
    __half2 h = __floats2half2_rn(lo, hi);
    return *reinterpret_cast<uint32_t*>(&h);
}
// swizzled halfword offset: 64 halves/row, 8 chunks of 8 halves (16B),
// chunk XOR (row&7) -> conflict-free ldmatrix
__device__ __forceinline__ int swz(int row, int chunk) {
    return row * 64 + ((chunk ^ (row & 7)) << 3);
}

// ============ merged pre-kernel: x + W1(masked) + W2 fp32 -> fp16, swizzled ============
__global__ void __launch_bounds__(256) convert_all_kernel(const float* __restrict__ x,
                                                          const float* __restrict__ W1,
                                                          const float* __restrict__ W2) {
    const int b = blockIdx.x;
    const int tid = threadIdx.x;
    if (b < 256) {
        const int g0 = b * 256 + tid;
        #pragma unroll
        for (int k = 0; k < 4; k++) {
            int g = g0 + k * 65536;
            float4 v = reinterpret_cast<const float4*>(x)[g];
            int row = g >> 4, c16 = g & 15;
            int chunk = c16 >> 1;
            half2* d = reinterpret_cast<half2*>(g_xh + row * 64 + ((chunk ^ (row & 7)) << 3) + (c16 & 1) * 4);
            d[0] = __floats2half2_rn(v.x, v.y);
            d[1] = __floats2half2_rn(v.z, v.w);
        }
    } else {
        const int g0 = (b - 256) * 256 + tid;
        #pragma unroll
        for (int k = 0; k < 2; k++) {
            int g = g0 + k * 32256;
            float4 v1 = reinterpret_cast<const float4*>(W1)[g];
            float4 v2 = reinterpret_cast<const float4*>(W2)[g];
            int net = g >> 10;
            int rem = g & 1023;
            int kk  = rem >> 4;
            int c16 = rem & 15;
            if (kk > net) v1 = make_float4(0.f, 0.f, 0.f, 0.f);   // autoregressive mask
            int chunk = c16 >> 1;
            int base = net * 4096 + kk * 64 + ((chunk ^ (kk & 7)) << 3) + (c16 & 1) * 4;
            half2* d1 = reinterpret_cast<half2*>(g_w1h + base);
            d1[0] = __floats2half2_rn(v1.x, v1.y);
            d1[1] = __floats2half2_rn(v1.z, v1.w);
            half2* d2 = reinterpret_cast<half2*>(g_w2h + base);
            d2[0] = __floats2half2_rn(v2.x, v2.y);
            d2[1] = __floats2half2_rn(v2.z, v2.w);
        }
    }
}

// ============ per-network body, layer-1 K-extent as compile-time constant ============
template<int KCN>
__device__ __forceinline__ void run_net(
    int iy, int m0, int lane, int warp,
    const half* sX, const half* sW1h, const half* sW2h, const half* sW3t,
    const float* sB1, const float* sB2, float b3s, float b3t,
    float* __restrict__ out)
{
    // layer-3 B fragments: 4 kc x {b0,b1}
    uint32_t b3f[4][2];
    {
        int krl = (lane & 7) + 8 * ((lane >> 3) & 1);
        #pragma unroll
        for (int kc = 0; kc < 4; kc++) {
            ldmx2t(b3f[kc][0], b3f[kc][1], smem_u32(sW3t + (kc * 16 + krl) * 8));
        }
    }

    // packed h1 (fp16x2) A-fragments for layer 2: [mt][16]
    uint32_t packed[4][16];

    // ================= PHASE 1: h1 = relu(X @ W1m + B1) =================
    #pragma unroll
    for (int j2h = 0; j2h < 2; j2h++) {
        uint32_t b1[KCN][2][4];
        #pragma unroll
        for (int kc = 0; kc < KCN; kc++) {
            #pragma unroll
            for (int j2l = 0; j2l < 2; j2l++) {
                int j2 = j2h * 2 + j2l;
                int kr = kc * 16 + (lane & 7) + 8 * ((lane >> 3) & 1);
                int chunk = j2 * 2 + (lane >> 4);
                ldmx4t(b1[kc][j2l][0], b1[kc][j2l][1], b1[kc][j2l][2], b1[kc][j2l][3],
                       smem_u32(sW1h + swz(kr, chunk)));
            }
        }
        #pragma unroll
        for (int mt = 0; mt < 4; mt++) {
            float acc[4][4];
            #pragma unroll
            for (int jj = 0; jj < 4; jj++) {   // bias-init accumulators
                int n0 = (j2h * 4 + jj) * 8 + 2 * (lane & 3);
                acc[jj][0] = sB1[n0];
                acc[jj][1] = sB1[n0 + 1];
                acc[jj][2] = acc[jj][0];
                acc[jj][3] = acc[jj][1];
            }
            #pragma unroll
            for (int kc = 0; kc < KCN; kc++) {
                uint32_t a0, a1, a2, a3;
                int r = warp * 64 + mt * 16 + (lane & 15);
                int chunk = kc * 2 + (lane >> 4);
                ldmx4(a0, a1, a2, a3, smem_u32(sX + swz(r, chunk)));
                #pragma unroll
                for (int j2l = 0; j2l < 2; j2l++) {
                    mma16816(acc[2 * j2l + 0], a0, a1, a2, a3, b1[kc][j2l][0], b1[kc][j2l][1]);
                    mma16816(acc[2 * j2l + 1], a0, a1, a2, a3, b1[kc][j2l][2], b1[kc][j2l][3]);
                }
            }
            #pragma unroll
            for (int jj = 0; jj < 4; jj++) {
                packed[mt][j2h * 8 + jj * 2 + 0] = packh2(fmaxf(acc[jj][0], 0.f), fmaxf(acc[jj][1], 0.f));
                packed[mt][j2h * 8 + jj * 2 + 1] = packh2(fmaxf(acc[jj][2], 0.f), fmaxf(acc[jj][3], 0.f));
            }
        }
    }

    // ====== PHASE 2+3: h2 = relu(h1 @ W2 + B2); [s,t] = h2 @ W3 + B3 (mma) ======
    float acc3[4][4];
    #pragma unroll
    for (int mt = 0; mt < 4; mt++) {
        acc3[mt][0] = b3s; acc3[mt][1] = b3t;
        acc3[mt][2] = b3s; acc3[mt][3] = b3t;
    }

    #pragma unroll
    for (int j2h = 0; j2h < 2; j2h++) {
        uint32_t b2[4][2][4];
        #pragma unroll
        for (int kc = 0; kc < 4; kc++) {
            #pragma unroll
            for (int j2l = 0; j2l < 2; j2l++) {
                int j2 = j2h * 2 + j2l;
                int kr = kc * 16 + (lane & 7) + 8 * ((lane >> 3) & 1);
                int chunk = j2 * 2 + (lane >> 4);
                ldmx4t(b2[kc][j2l][0], b2[kc][j2l][1], b2[kc][j2l][2], b2[kc][j2l][3],
                       smem_u32(sW2h + swz(kr, chunk)));
            }
        }
        #pragma unroll
        for (int mt = 0; mt < 4; mt++) {
            float acc[4][4];
            #pragma unroll
            for (int jj = 0; jj < 4; jj++) {   // bias-init accumulators
                int n0 = (j2h * 4 + jj) * 8 + 2 * (lane & 3);
                acc[jj][0] = sB2[n0];
                acc[jj][1] = sB2[n0 + 1];
                acc[jj][2] = acc[jj][0];
                acc[jj][3] = acc[jj][1];
            }
            #pragma unroll
            for (int kc = 0; kc < 4; kc++) {
                const uint32_t* a = &packed[mt][4 * kc];
                #pragma unroll
                for (int j2l = 0; j2l < 2; j2l++) {
                    mma16816(acc[2 * j2l + 0], a[0], a[1], a[2], a[3], b2[kc][j2l][0], b2[kc][j2l][1]);
                    mma16816(acc[2 * j2l + 1], a[0], a[1], a[2], a[3], b2[kc][j2l][2], b2[kc][j2l][3]);
                }
            }
            // relu + pack h2 -> layer-3 A fragments (this j2h covers k = j2h*32..+31)
            uint32_t p2[8];
            #pragma unroll
            for (int jj = 0; jj < 4; jj++) {
                p2[jj * 2 + 0] = packh2(fmaxf(acc[jj][0], 0.f), fmaxf(acc[jj][1], 0.f));
                p2[jj * 2 + 1] = packh2(fmaxf(acc[jj][2], 0.f), fmaxf(acc[jj][3], 0.f));
            }
            mma16816(acc3[mt], p2[0], p2[1], p2[2], p2[3], b3f[j2h * 2 + 0][0], b3f[j2h * 2 + 0][1]);
            mma16816(acc3[mt], p2[4], p2[5], p2[6], p2[7], b3f[j2h * 2 + 1][0], b3f[j2h * 2 + 1][1]);
        }
    }

    // ---- store: lanes (lane&3)==0 hold cols 0 (scale) and 1 (translation) ----
    #pragma unroll
    for (int mt = 0; mt < 4; mt++) {
        if ((lane & 3) == 0) {
            int row = m0 + warp * 64 + mt * 16 + (lane >> 2);
            out[row * DIM + iy] = fminf(fmaxf(acc3[mt][0], -5.f), 5.f);
            out[BATCH * DIM + row * DIM + iy] = acc3[mt][1];
            int row8 = row + 8;
            out[row8 * DIM + iy] = fminf(fmaxf(acc3[mt][2], -5.f), 5.f);
            out[BATCH * DIM + row8 * DIM + iy] = acc3[mt][3];
        }
    }
}

// ============ main kernel ============
// grid (BATCH/TROWS, DIM): one 256-row tile, one network per CTA. No mid-kernel barriers.
__global__ void __launch_bounds__(THREADS, 3)
ar_kernel(const float* __restrict__ w0, const float* __restrict__ b0,
          const float* __restrict__ v0, const float* __restrict__ c0,
          const float* __restrict__ B1, const float* __restrict__ B2,
          const float* __restrict__ W3, const float* __restrict__ B3,
          float* __restrict__ out)
{
    const int tid = threadIdx.x;
    const int iy  = blockIdx.y;   // network index 0..63
    const int m0  = blockIdx.x * TROWS;

    if (iy == 0) {
        float s = c0[0], t = c0[1];
        #pragma unroll
        for (int j = 0; j < HID; j++) {
            float h = fmaxf(w0[j] + b0[j], 0.f);
            s += h * v0[j * 2 + 0];
            t += h * v0[j * 2 + 1];
        }
        s = fminf(fmaxf(s, -5.f), 5.f);
        #pragma unroll
        for (int k = 0; k < TROWS; k += THREADS) {
            int r = m0 + k + tid;
            out[r * DIM + 0] = s;
            out[BATCH * DIM + r * DIM + 0] = t;
        }
        return;
    }

    const int i = iy - 1;
    const int kcN = (iy + 15) >> 4;   // masked K chunks for layer 1 (1..4)

    __shared__ __align__(16) half  sX[TROWS * 64];  // 32 KB
    __shared__ __align__(16) half  sW1h[64 * 64];   //  8 KB
    __shared__ __align__(16) half  sW2h[64 * 64];   //  8 KB
    __shared__ __align__(16) half  sW3t[64 * 8];    //  1 KB  [k][n<=8] layer-3 mma B
    __shared__ float sB1[64], sB2[64];

    const float b3s = B3[i * 2 + 0];
    const float b3t = B3[i * 2 + 1];

    // ---- async fetch: weights (8KB each) + x tile (32KB = 2048 x 16B) ----
    {
        const uint32_t a1 = smem_u32(sW1h), a2 = smem_u32(sW2h);
        const half* gw1 = g_w1h + i * 4096;
        const half* gw2 = g_w2h + i * 4096;
        #pragma unroll
        for (int r = 0; r < 4; r++) {
            int c = r * THREADS + tid;
            cp16(a1 + c * 16, gw1 + c * 8);
            cp16(a2 + c * 16, gw2 + c * 8);
        }
        const uint32_t ax = smem_u32(sX);
        const half* gx = g_xh + (size_t)m0 * 64;
        #pragma unroll
        for (int r = 0; r < 16; r++) {         // FIXED: 16 x 128 x 16B = 32 KB (was 8 -> half tile)
            int c = r * THREADS + tid;
            cp16(ax + c * 16, gx + c * 8);
        }
        if (tid < 64)  { sB1[tid] = B1[i * 64 + tid]; sB2[tid] = B2[i * 64 + tid]; }
        // W3 transposed tile: row k (0..63), col n (0..7); n<2 real, rest zero
        if (tid < 64) {
            half2* d = reinterpret_cast<half2*>(sW3t + tid * 8);
            d[0] = __floats2half2_rn(W3[i * 128 + tid * 2 + 0], W3[i * 128 + tid * 2 + 1]);
            d[1] = __floats2half2_rn(0.f, 0.f);
            d[2] = __floats2half2_rn(0.f, 0.f);
            d[3] = __floats2half2_rn(0.f, 0.f);
        }
    }
    cp_commit();
    cp_wait_all();
    __syncthreads();

    const int lane = tid & 31;
    const int warp = tid >> 5;

    switch (kcN) {
        case 1: run_net<1>(iy, m0, lane, warp, sX, sW1h, sW2h, sW3t, sB1, sB2, b3s, b3t, out); break;
        case 2: run_net<2>(iy, m0, lane, warp, sX, sW1h, sW2h, sW3t, sB1, sB2, b3s, b3t, out); break;
        case 3: run_net<3>(iy, m0, lane, warp, sX, sW1h, sW2h, sW3t, sB1, sB2, b3s, b3t, out); break;
        default: run_net<4>(iy, m0, lane, warp, sX, sW1h, sW2h, sW3t, sB1, sB2, b3s, b3t, out); break;
    }
}

extern "C" void kernel_launch(void* const* d_in, const int* in_sizes, int n_in,
                              void* d_out, int out_size) {
    const float* x  = (const float*)d_in[0];
    const float* w0 = (const float*)d_in[1];
    const float* b0 = (const float*)d_in[2];
    const float* v0 = (const float*)d_in[3];
    const float* c0 = (const float*)d_in[4];
    const float* W1 = (const float*)d_in[5];
    const float* B1 = (const float*)d_in[6];
    const float* W2 = (const float*)d_in[7];
    const float* B2 = (const float*)d_in[8];
    const float* W3 = (const float*)d_in[9];
    const float* B3 = (const float*)d_in[10];

    convert_all_kernel<<<382, 256>>>(x, W1, W2);

    dim3 grid(BATCH / TROWS, DIM);   // 64 x 64 = 4096 CTAs
    ar_kernel<<<grid, THREADS>>>(w0, b0, v0, c0, B1, B2, W3, B3, (float*)d_out);
}